// round 15
// baseline (speedup 1.0000x reference)
#include <cuda_runtime.h>
#include <cuda_fp16.h>

#define K   8
#define D   16
#define NN  32
#define TT  200
#define T2  400         // two batches merged per sort
#define BB  2048
#define NPAIR 1024
#define LOG2PI 1.8378770664093453f
#define TPB 256
#define GRID 592

// ---- word (4B) offsets; param image [0, W_PAR) identical in gmem & smem ----
#define W_EM   0       // -C fp16 rows: s*384 + n*12 + w (w=0..7 used)
#define W_DY   3072    // -A fp16 rows: s*192 + d*12 + w
#define W_EOF  4608    // -em_off f32: s*32 + n
#define W_EA2  4864    // exp(-2*em_ls) f32: s*32 + n
#define W_DOF  5120    // -dyn_off f32: s*16 + d
#define W_DA2  5248    // 1/dyn_scale^2 f32: s*16 + d
#define W_INA  5376    // e^{-init_ls} f32: s*16 + d
#define W_INB  5504    // -loc*e^{-init_ls} f32: s*16 + d
#define W_TR   5632    // 64
#define W_C0   5696    // 8
#define W_CT   5704    // 8
#define W_PAR  5712
// block-local smem (obs streamed from gmem)
#define W_Z    5712                 // z fp16 pairs: slot e*8 + dpair (400*8)
#define W_SS   (W_Z + T2*8)         // 8912: raw state per slot (400)
#define W_TOF  (W_SS + T2)          // 9312: rank -> slot (400)
#define W_CNT  (W_TOF + T2)         // 9712: 16 groups x 8 states
#define W_TILE (W_CNT + 128)        // 9840: packed tiles (<= 33)
#define W_NT   (W_TILE + 40)        // 9880
#define W_TOT  9884                 // 39.5 KB

__device__ __align__(16) unsigned int g_par[W_PAR];

#define H2(x) (*reinterpret_cast<const __half2*>(&(x)))

__device__ __forceinline__ void mma16816(float& d0, float& d1, float& d2, float& d3,
    unsigned a0, unsigned a1, unsigned a2, unsigned a3,
    unsigned b0, unsigned b1,
    float c0, float c1, float c2, float c3)
{
    asm("mma.sync.aligned.m16n8k16.row.col.f32.f16.f16.f32 "
        "{%0,%1,%2,%3}, {%4,%5,%6,%7}, {%8,%9}, {%10,%11,%12,%13};"
        : "=f"(d0), "=f"(d1), "=f"(d2), "=f"(d3)
        : "r"(a0), "r"(a1), "r"(a2), "r"(a3), "r"(b0), "r"(b1),
          "f"(c0), "f"(c1), "f"(c2), "f"(c3));
}

// ---------- prep: one element per thread, writes final packed image ----------
__global__ __launch_bounds__(256)
void prep_kernel(const float* __restrict__ init_logits,
                 const float* __restrict__ init_locs,
                 const float* __restrict__ init_ls,
                 const float* __restrict__ trans_logits,
                 const float* __restrict__ dynM,
                 const float* __restrict__ dynOff,
                 const float* __restrict__ dynLS,
                 const float* __restrict__ emM,
                 const float* __restrict__ emOff,
                 const float* __restrict__ emLS)
{
    float* gf = reinterpret_cast<float*>(g_par);
    __half* gh = reinterpret_cast<__half*>(g_par);
    const int g = blockIdx.x * 256 + threadIdx.x;
    if (g < 4096) {
        int i = g, s = i >> 9, r = i & 511, n = r >> 4, d = r & 15;
        gh[(W_EM + s * 384 + n * 12) * 2 + d] = __float2half(-emM[i]);
    } else if (g < 6144) {
        int i = g - 4096, s = i >> 8, r = i & 255, dd = r >> 4, j = r & 15;
        gh[(W_DY + s * 192 + dd * 12) * 2 + j] = __float2half(-dynM[i]);
    } else if (g < 6400) {
        int i = g - 6144, s = i >> 5, n = i & 31;
        gf[W_EOF + s * 32 + n] = -emOff[i];
        gf[W_EA2 + s * 32 + n] = expf(-2.0f * emLS[i]);
    } else if (g < 6528) {
        int i = g - 6400, s = i >> 4, d = i & 15;
        gf[W_DOF + s * 16 + d] = -dynOff[i];
        float sc = dynLS[i];
        gf[W_DA2 + s * 16 + d] = 1.0f / (sc * sc);
        float ai = expf(-init_ls[i]);
        gf[W_INA + s * 16 + d] = ai;
        gf[W_INB + s * 16 + d] = -init_locs[i] * ai;
    } else if (g < 6592) {
        int i = g - 6528, sp = i >> 3;
        float m = -1e30f;
        for (int k = 0; k < K; k++) m = fmaxf(m, trans_logits[sp * K + k]);
        float sum = 0.0f;
        for (int k = 0; k < K; k++) sum += expf(trans_logits[sp * K + k] - m);
        gf[W_TR + i] = trans_logits[i] - m - logf(sum);
    } else if (g < 6600) {
        int s = g - 6592;
        float emc = -16.0f * LOG2PI;
        for (int n = 0; n < NN; n++) emc -= emLS[s * NN + n];
        float dync = -8.0f * LOG2PI;
        for (int d = 0; d < D; d++) dync -= logf(dynLS[s * D + d]);
        float initc = -8.0f * LOG2PI;
        for (int d = 0; d < D; d++) initc -= init_ls[s * D + d];
        float m = -1e30f;
        for (int k = 0; k < K; k++) m = fmaxf(m, init_logits[k]);
        float sum = 0.0f;
        for (int k = 0; k < K; k++) sum += expf(init_logits[k] - m);
        gf[W_C0 + s] = (init_logits[s] - m - logf(sum)) + initc + emc;
        gf[W_CT + s] = emc + dync;
    }
}

// ---------- main: persistent blocks; 2 batches sorted together per iteration ----------
__global__ __launch_bounds__(TPB, 4)
void stage1_kernel(const int*   __restrict__ ds,
                   const float* __restrict__ cont,
                   const float* __restrict__ obs,
                   float*       __restrict__ out)
{
    __shared__ __align__(16) unsigned int sm[W_TOT];
    __shared__ float sRed0[TPB / 32], sRed1[TPB / 32];
    float* smf = reinterpret_cast<float*>(sm);
    int* smi = reinterpret_cast<int*>(sm);
    const int tid = threadIdx.x;
    const int lane = tid & 31;
    const int warpid = tid >> 5;
    const int g = lane >> 2;
    const int tig = lane & 3;

    // params image -> smem ONCE per block
    {
        const uint4* src = reinterpret_cast<const uint4*>(g_par);
        uint4* dst = reinterpret_cast<uint4*>(sm);
        #pragma unroll
        for (int i2 = 0; i2 < (W_PAR / 4 + TPB - 1) / TPB; i2++) {
            int i = tid + i2 * TPB;
            if (i < W_PAR / 4) dst[i] = src[i];
        }
    }

    for (int pb = blockIdx.x; pb < NPAIR; pb += GRID) {
        const int ebase = pb * T2;   // slot e maps to (ds|cont|obs)[ebase + e]

        // states first (sort's critical dependency). pass0: e=tid (all <400);
        // pass1: e=256+tid for tid<144.
        const int s0 = ds[ebase + tid];
        const bool act1 = tid < (T2 - TPB);
        const int s1 = act1 ? ds[ebase + TPB + tid] : 8;

        // cont -> smem fp16 pairs, slot-row stride 8 (400*4 float4)
        {
            const float4* src = reinterpret_cast<const float4*>(cont) + (size_t)ebase * 4;
            #pragma unroll
            for (int i2 = 0; i2 < 7; i2++) {
                int i = tid + i2 * TPB;
                if (i < T2 * 4) {
                    float4 v = src[i];
                    int e = i >> 2, q = i & 3;
                    __half2 h0 = __floats2half2_rn(v.x, v.y);
                    __half2 h1 = __floats2half2_rn(v.z, v.w);
                    *reinterpret_cast<uint2*>(sm + W_Z + e * 8 + q * 2) =
                        make_uint2(*reinterpret_cast<unsigned*>(&h0), *reinterpret_cast<unsigned*>(&h1));
                }
            }
        }
        smi[W_SS + tid] = s0;
        if (act1) smi[W_SS + TPB + tid] = s1;
        if (tid < 128) smi[W_CNT + tid] = 0;
        __syncthreads();

        // per-warp counts via match; groups 0..7 = pass0, 8..15 = pass1
        unsigned mt0 = __match_any_sync(0xFFFFFFFFu, s0);
        int before0 = __popc(mt0 & ((1u << lane) - 1u));
        if (before0 == 0) smi[W_CNT + warpid * 8 + s0] = __popc(mt0);
        unsigned mt1 = __match_any_sync(0xFFFFFFFFu, s1);
        int before1 = __popc(mt1 & ((1u << lane) - 1u));
        if (act1 && before1 == 0) smi[W_CNT + (8 + warpid) * 8 + s1] = __popc(mt1);
        __syncthreads();

        // parallel scan + tile build (warp 0)
        if (warpid == 0) {
            int tot = 0;
            if (lane < 8) {
                #pragma unroll
                for (int w = 0; w < 16; w++) tot += smi[W_CNT + w * 8 + lane];
            }
            int sc = tot;
            #pragma unroll
            for (int o = 1; o < 8; o <<= 1) {
                int v = __shfl_up_sync(0xFFFFFFFFu, sc, o);
                if (lane >= o) sc += v;
            }
            int base = sc - tot;
            if (lane < 8) {
                int run = base;
                #pragma unroll
                for (int w = 0; w < 16; w++) {
                    int c = smi[W_CNT + w * 8 + lane];
                    smi[W_CNT + w * 8 + lane] = run;
                    run += c;
                }
            }
            int ntk = (lane < 8) ? ((tot + 15) >> 4) : 0;
            int tsc = ntk;
            #pragma unroll
            for (int o = 1; o < 8; o <<= 1) {
                int v = __shfl_up_sync(0xFFFFFFFFu, tsc, o);
                if (lane >= o) tsc += v;
            }
            int tbase = tsc - ntk;
            if (lane < 8) {
                for (int j = 0; j < ntk; j++) {
                    int cnt = min(16, tot - 16 * j);
                    smi[W_TILE + tbase + j] = (lane << 14) | ((base + 16 * j) << 5) | cnt;
                }
                if (lane == 7) smi[W_NT] = tsc;
            }
        }
        __syncthreads();
        smi[W_TOF + smi[W_CNT + warpid * 8 + s0] + before0] = tid;
        if (act1) smi[W_TOF + smi[W_CNT + (8 + warpid) * 8 + s1] + before1] = TPB + tid;
        __syncthreads();

        const int nt = smi[W_NT];
        const float* obsb = obs + (size_t)ebase * NN;
        float part0 = 0.0f, part1 = 0.0f;

        for (int tile = warpid; tile < nt; tile += 8) {
            const int pk = smi[W_TILE + tile];
            const int cnt = pk & 31;
            const int rbase = (pk >> 5) & 511;
            const int s = pk >> 14;
            const bool v0 = g < cnt, v1 = g + 8 < cnt;
            const int t0 = smi[W_TOF + rbase + (v0 ? g : 0)];
            const int t1 = smi[W_TOF + rbase + (v1 ? g + 8 : 0)];
            const bool f0 = (t0 == 0) | (t0 == TT);   // first timestep of its batch
            const bool f1 = (t1 == 0) | (t1 == TT);

            unsigned a0 = sm[W_Z + t0 * 8 + tig];
            unsigned a1 = sm[W_Z + t1 * 8 + tig];
            unsigned a2 = sm[W_Z + t0 * 8 + tig + 4];
            unsigned a3 = sm[W_Z + t1 * 8 + tig + 4];

            // obs rows streamed from gmem (single-use)
            const float* orow0 = obsb + t0 * NN + 2 * tig;
            const float* orow1 = obsb + t1 * NN + 2 * tig;
            float2 qa0[4], qa1[4];
            #pragma unroll
            for (int c = 0; c < 4; c++) {
                qa0[c] = __ldcs(reinterpret_cast<const float2*>(orow0 + 8 * c));
                qa1[c] = __ldcs(reinterpret_cast<const float2*>(orow1 + 8 * c));
            }

            // emission: 4 n-tiles
            float acc0 = 0.0f, acc1 = 0.0f;
            #pragma unroll
            for (int ntl = 0; ntl < 4; ntl++) {
                const unsigned* Cb = sm + W_EM + s * 384 + (ntl * 8 + g) * 12;
                unsigned b0 = Cb[tig], b1 = Cb[tig + 4];
                float2 e = *reinterpret_cast<const float2*>(smf + W_EOF + s * 32 + ntl * 8 + 2 * tig);
                float d0, d1, d2, d3;
                mma16816(d0, d1, d2, d3, a0, a1, a2, a3, b0, b1,
                         qa0[ntl].x + e.x, qa0[ntl].y + e.y, qa1[ntl].x + e.x, qa1[ntl].y + e.y);
                float2 ea = *reinterpret_cast<const float2*>(smf + W_EA2 + s * 32 + ntl * 8 + 2 * tig);
                acc0 = fmaf(ea.x, d0 * d0, acc0); acc0 = fmaf(ea.y, d1 * d1, acc0);
                acc1 = fmaf(ea.x, d2 * d2, acc1); acc1 = fmaf(ea.y, d3 * d3, acc1);
            }

            // dynamics: 2 n-tiles
            int tp0 = f0 ? t0 : t0 - 1;
            int tp1 = f1 ? t1 : t1 - 1;
            unsigned p0 = sm[W_Z + tp0 * 8 + tig];
            unsigned p1 = sm[W_Z + tp1 * 8 + tig];
            unsigned p2 = sm[W_Z + tp0 * 8 + tig + 4];
            unsigned p3 = sm[W_Z + tp1 * 8 + tig + 4];
            float dac0 = 0.0f, dac1 = 0.0f;
            #pragma unroll
            for (int ntl = 0; ntl < 2; ntl++) {
                const unsigned* Ab = sm + W_DY + s * 192 + (ntl * 8 + g) * 12;
                unsigned b0 = Ab[tig], b1 = Ab[tig + 4];
                float2 df = *reinterpret_cast<const float2*>(smf + W_DOF + s * 16 + ntl * 8 + 2 * tig);
                float2 q0 = __half22float2(H2(sm[W_Z + t0 * 8 + ntl * 4 + tig]));
                float2 q1 = __half22float2(H2(sm[W_Z + t1 * 8 + ntl * 4 + tig]));
                float d0, d1, d2, d3;
                mma16816(d0, d1, d2, d3, p0, p1, p2, p3, b0, b1,
                         q0.x + df.x, q0.y + df.y, q1.x + df.x, q1.y + df.y);
                float2 da = *reinterpret_cast<const float2*>(smf + W_DA2 + s * 16 + ntl * 8 + 2 * tig);
                dac0 = fmaf(da.x, d0 * d0, dac0); dac0 = fmaf(da.y, d1 * d1, dac0);
                dac1 = fmaf(da.x, d2 * d2, dac1); dac1 = fmaf(da.y, d3 * d3, dac1);
            }

            float row0 = v0 ? (acc0 + (f0 ? 0.0f : dac0)) : 0.0f;
            float row1 = v1 ? (acc1 + (f1 ? 0.0f : dac1)) : 0.0f;
            row0 += __shfl_xor_sync(0xFFFFFFFFu, row0, 1);
            row0 += __shfl_xor_sync(0xFFFFFFFFu, row0, 2);
            row1 += __shfl_xor_sync(0xFFFFFFFFu, row1, 1);
            row1 += __shfl_xor_sync(0xFFFFFFFFu, row1, 2);

            if (tig == 0) {
                if (v0) {
                    float lp;
                    if (!f0) lp = smf[W_CT + s] + smf[W_TR + smi[W_SS + t0 - 1] * 8 + s];
                    else {
                        float iacc = 0.0f;
                        lp = smf[W_C0 + s];
                        #pragma unroll
                        for (int w = 0; w < 8; w++) {
                            float2 z = __half22float2(H2(sm[W_Z + t0 * 8 + w]));
                            float y0 = fmaf(z.x, smf[W_INA + s * 16 + 2 * w], smf[W_INB + s * 16 + 2 * w]);
                            float y1 = fmaf(z.y, smf[W_INA + s * 16 + 2 * w + 1], smf[W_INB + s * 16 + 2 * w + 1]);
                            iacc = fmaf(y0, y0, iacc); iacc = fmaf(y1, y1, iacc);
                        }
                        lp -= 0.5f * iacc;
                    }
                    float contrib = lp - 0.5f * row0;
                    if (t0 >= TT) part1 += contrib; else part0 += contrib;
                }
                if (v1) {
                    float lp;
                    if (!f1) lp = smf[W_CT + s] + smf[W_TR + smi[W_SS + t1 - 1] * 8 + s];
                    else {
                        float iacc = 0.0f;
                        lp = smf[W_C0 + s];
                        #pragma unroll
                        for (int w = 0; w < 8; w++) {
                            float2 z = __half22float2(H2(sm[W_Z + t1 * 8 + w]));
                            float y0 = fmaf(z.x, smf[W_INA + s * 16 + 2 * w], smf[W_INB + s * 16 + 2 * w]);
                            float y1 = fmaf(z.y, smf[W_INA + s * 16 + 2 * w + 1], smf[W_INB + s * 16 + 2 * w + 1]);
                            iacc = fmaf(y0, y0, iacc); iacc = fmaf(y1, y1, iacc);
                        }
                        lp -= 0.5f * iacc;
                    }
                    float contrib = lp - 0.5f * row1;
                    if (t1 >= TT) part1 += contrib; else part0 += contrib;
                }
            }
        }

        // block reduction for both batches (fixed assignment -> deterministic)
        #pragma unroll
        for (int o = 16; o > 0; o >>= 1) {
            part0 += __shfl_xor_sync(0xFFFFFFFFu, part0, o);
            part1 += __shfl_xor_sync(0xFFFFFFFFu, part1, o);
        }
        if (lane == 0) { sRed0[warpid] = part0; sRed1[warpid] = part1; }
        __syncthreads();
        if (tid == 0) {
            float sum0 = 0.0f, sum1 = 0.0f;
            #pragma unroll
            for (int w = 0; w < TPB / 32; w++) { sum0 += sRed0[w]; sum1 += sRed1[w]; }
            out[2 * pb] = sum0;
            out[2 * pb + 1] = sum1;
        }
    }
}

extern "C" void kernel_launch(void* const* d_in, const int* in_sizes, int n_in,
                              void* d_out, int out_size)
{
    const int*   ds    = (const int*)  d_in[0];
    const float* cont  = (const float*)d_in[1];
    const float* obs   = (const float*)d_in[2];
    const float* il    = (const float*)d_in[3];
    const float* iloc  = (const float*)d_in[4];
    const float* ils   = (const float*)d_in[5];
    const float* trl   = (const float*)d_in[6];
    const float* dynM  = (const float*)d_in[7];
    const float* dynO  = (const float*)d_in[8];
    const float* dynS  = (const float*)d_in[9];
    const float* emM   = (const float*)d_in[10];
    const float* emO   = (const float*)d_in[11];
    const float* emS   = (const float*)d_in[12];
    float* out = (float*)d_out;

    prep_kernel<<<26, 256>>>(il, iloc, ils, trl, dynM, dynO, dynS, emM, emO, emS);
    stage1_kernel<<<GRID, TPB>>>(ds, cont, obs, out);
}

// round 16
// speedup vs baseline: 1.0823x; 1.0823x over previous
#include <cuda_runtime.h>
#include <cuda_fp16.h>

#define K   8
#define D   16
#define NN  32
#define TT  200
#define T2  400         // two batches merged per sort
#define BB  2048
#define NPAIR 1024
#define LOG2PI 1.8378770664093453f
#define TPB 256
#define GRID 592

// ---- smem word (4B) offsets ----
#define W_EM   0       // -C fp16 rows: s*384 + n*12 + w (w=0..7 used)
#define W_DY   3072    // -A fp16 rows: s*192 + d*12 + w
#define W_EOF  4608    // -em_off f32: s*32 + n
#define W_EA2  4864    // exp(-2*em_ls) f32: s*32 + n
#define W_DOF  5120    // -dyn_off f32: s*16 + d
#define W_DA2  5248    // 1/dyn_scale^2 f32: s*16 + d
#define W_INA  5376    // e^{-init_ls} f32: s*16 + d
#define W_INB  5504    // -loc*e^{-init_ls} f32: s*16 + d
#define W_TR   5632    // 64
#define W_C0   5696    // 8
#define W_CT   5704    // 8
#define W_PAR  5712
// block-local (obs streamed from gmem)
#define W_Z    5712                 // z fp16 pairs: slot e*8 + dpair (400*8)
#define W_SS   (W_Z + T2*8)         // raw state per slot (400)
#define W_TOF  (W_SS + T2)          // rank -> slot (400)
#define W_CNT  (W_TOF + T2)         // 16 groups x 8 states
#define W_TILE (W_CNT + 128)        // packed tiles (<= 33)
#define W_NT   (W_TILE + 40)
#define W_TOT  (W_NT + 4)           // 39.5 KB

#define H2(x) (*reinterpret_cast<const __half2*>(&(x)))

__device__ __forceinline__ void mma16816(float& d0, float& d1, float& d2, float& d3,
    unsigned a0, unsigned a1, unsigned a2, unsigned a3,
    unsigned b0, unsigned b1,
    float c0, float c1, float c2, float c3)
{
    asm("mma.sync.aligned.m16n8k16.row.col.f32.f16.f16.f32 "
        "{%0,%1,%2,%3}, {%4,%5,%6,%7}, {%8,%9}, {%10,%11,%12,%13};"
        : "=f"(d0), "=f"(d1), "=f"(d2), "=f"(d3)
        : "r"(a0), "r"(a1), "r"(a2), "r"(a3), "r"(b0), "r"(b1),
          "f"(c0), "f"(c1), "f"(c2), "f"(c3));
}

// ---------- single kernel: per-block param build + persistent pair loop ----------
__global__ __launch_bounds__(TPB, 4)
void stage1_kernel(const int*   __restrict__ ds,
                   const float* __restrict__ cont,
                   const float* __restrict__ obs,
                   const float* __restrict__ init_logits,
                   const float* __restrict__ init_locs,
                   const float* __restrict__ init_ls,
                   const float* __restrict__ trans_logits,
                   const float* __restrict__ dynM,
                   const float* __restrict__ dynOff,
                   const float* __restrict__ dynLS,
                   const float* __restrict__ emM,
                   const float* __restrict__ emOff,
                   const float* __restrict__ emLS,
                   float*       __restrict__ out)
{
    __shared__ __align__(16) unsigned int sm[W_TOT];
    __shared__ float sRed0[TPB / 32], sRed1[TPB / 32];
    float* smf = reinterpret_cast<float*>(sm);
    int* smi = reinterpret_cast<int*>(sm);
    __half* smh = reinterpret_cast<__half*>(sm);
    const int tid = threadIdx.x;
    const int lane = tid & 31;
    const int warpid = tid >> 5;
    const int g = lane >> 2;
    const int tig = lane & 3;

    // ---- one-time param image build (per block; inputs L2-hot after wave 1) ----
    #pragma unroll
    for (int i2 = 0; i2 < 16; i2++) {              // emission -C fp16
        int i = tid + i2 * TPB;                    // K*NN*D = 4096
        int s = i >> 9, r = i & 511, n = r >> 4, d = r & 15;
        smh[(W_EM + s * 384 + n * 12) * 2 + d] = __float2half(-emM[i]);
    }
    #pragma unroll
    for (int i2 = 0; i2 < 8; i2++) {               // dynamics -A fp16
        int i = tid + i2 * TPB;                    // K*D*D = 2048
        int s = i >> 8, r = i & 255, dd = r >> 4, j = r & 15;
        smh[(W_DY + s * 192 + dd * 12) * 2 + j] = __float2half(-dynM[i]);
    }
    {                                              // emission epilogue (256 = TPB)
        int i = tid, s = i >> 5, n = i & 31;
        smf[W_EOF + s * 32 + n] = -emOff[i];
        smf[W_EA2 + s * 32 + n] = expf(-2.0f * emLS[i]);
    }
    if (tid < K * D) {                             // dyn epilogue + init (128)
        int i = tid, s = i >> 4, d = i & 15;
        smf[W_DOF + s * 16 + d] = -dynOff[i];
        float sc = dynLS[i];
        smf[W_DA2 + s * 16 + d] = 1.0f / (sc * sc);
        float ai = expf(-init_ls[i]);
        smf[W_INA + s * 16 + d] = ai;
        smf[W_INB + s * 16 + d] = -init_locs[i] * ai;
    } else if (tid < 128 + K * K) {                // log-softmax transitions (64)
        int i = tid - 128, sp = i >> 3;
        float m = -1e30f;
        for (int k = 0; k < K; k++) m = fmaxf(m, trans_logits[sp * K + k]);
        float sum = 0.0f;
        for (int k = 0; k < K; k++) sum += expf(trans_logits[sp * K + k] - m);
        smf[W_TR + i] = trans_logits[i] - m - logf(sum);
    } else if (tid < 192 + K) {                    // per-state constants (8)
        int s = tid - 192;
        float emc = -16.0f * LOG2PI;
        for (int n = 0; n < NN; n++) emc -= emLS[s * NN + n];
        float dync = -8.0f * LOG2PI;
        for (int d = 0; d < D; d++) dync -= logf(dynLS[s * D + d]);
        float initc = -8.0f * LOG2PI;
        for (int d = 0; d < D; d++) initc -= init_ls[s * D + d];
        float m = -1e30f;
        for (int k = 0; k < K; k++) m = fmaxf(m, init_logits[k]);
        float sum = 0.0f;
        for (int k = 0; k < K; k++) sum += expf(init_logits[k] - m);
        smf[W_C0 + s] = (init_logits[s] - m - logf(sum)) + initc + emc;
        smf[W_CT + s] = emc + dync;
    }
    __syncthreads();

    // ---- persistent pair loop (2 batches per sort) ----
    for (int pb = blockIdx.x; pb < NPAIR; pb += GRID) {
        const int ebase = pb * T2;

        const int s0 = ds[ebase + tid];
        const bool act1 = tid < (T2 - TPB);
        const int s1 = act1 ? ds[ebase + TPB + tid] : 8;

        // cont -> smem fp16 pairs, slot-row stride 8
        {
            const float4* src = reinterpret_cast<const float4*>(cont) + (size_t)ebase * 4;
            #pragma unroll
            for (int i2 = 0; i2 < 7; i2++) {
                int i = tid + i2 * TPB;
                if (i < T2 * 4) {
                    float4 v = src[i];
                    int e = i >> 2, q = i & 3;
                    __half2 h0 = __floats2half2_rn(v.x, v.y);
                    __half2 h1 = __floats2half2_rn(v.z, v.w);
                    *reinterpret_cast<uint2*>(sm + W_Z + e * 8 + q * 2) =
                        make_uint2(*reinterpret_cast<unsigned*>(&h0), *reinterpret_cast<unsigned*>(&h1));
                }
            }
        }
        smi[W_SS + tid] = s0;
        if (act1) smi[W_SS + TPB + tid] = s1;
        if (tid < 128) smi[W_CNT + tid] = 0;
        __syncthreads();

        unsigned mt0 = __match_any_sync(0xFFFFFFFFu, s0);
        int before0 = __popc(mt0 & ((1u << lane) - 1u));
        if (before0 == 0) smi[W_CNT + warpid * 8 + s0] = __popc(mt0);
        unsigned mt1 = __match_any_sync(0xFFFFFFFFu, s1);
        int before1 = __popc(mt1 & ((1u << lane) - 1u));
        if (act1 && before1 == 0) smi[W_CNT + (8 + warpid) * 8 + s1] = __popc(mt1);
        __syncthreads();

        if (warpid == 0) {
            int tot = 0;
            if (lane < 8) {
                #pragma unroll
                for (int w = 0; w < 16; w++) tot += smi[W_CNT + w * 8 + lane];
            }
            int sc = tot;
            #pragma unroll
            for (int o = 1; o < 8; o <<= 1) {
                int v = __shfl_up_sync(0xFFFFFFFFu, sc, o);
                if (lane >= o) sc += v;
            }
            int base = sc - tot;
            if (lane < 8) {
                int run = base;
                #pragma unroll
                for (int w = 0; w < 16; w++) {
                    int c = smi[W_CNT + w * 8 + lane];
                    smi[W_CNT + w * 8 + lane] = run;
                    run += c;
                }
            }
            int ntk = (lane < 8) ? ((tot + 15) >> 4) : 0;
            int tsc = ntk;
            #pragma unroll
            for (int o = 1; o < 8; o <<= 1) {
                int v = __shfl_up_sync(0xFFFFFFFFu, tsc, o);
                if (lane >= o) tsc += v;
            }
            int tbase = tsc - ntk;
            if (lane < 8) {
                for (int j = 0; j < ntk; j++) {
                    int cnt = min(16, tot - 16 * j);
                    smi[W_TILE + tbase + j] = (lane << 14) | ((base + 16 * j) << 5) | cnt;
                }
                if (lane == 7) smi[W_NT] = tsc;
            }
        }
        __syncthreads();
        smi[W_TOF + smi[W_CNT + warpid * 8 + s0] + before0] = tid;
        if (act1) smi[W_TOF + smi[W_CNT + (8 + warpid) * 8 + s1] + before1] = TPB + tid;
        __syncthreads();

        const int nt = smi[W_NT];
        const float* obsb = obs + (size_t)ebase * NN;
        float part0 = 0.0f, part1 = 0.0f;

        for (int tile = warpid; tile < nt; tile += 8) {
            const int pk = smi[W_TILE + tile];
            const int cnt = pk & 31;
            const int rbase = (pk >> 5) & 511;
            const int s = pk >> 14;
            const bool v0 = g < cnt, v1 = g + 8 < cnt;
            const int t0 = smi[W_TOF + rbase + (v0 ? g : 0)];
            const int t1 = smi[W_TOF + rbase + (v1 ? g + 8 : 0)];
            const bool f0 = (t0 == 0) | (t0 == TT);
            const bool f1 = (t1 == 0) | (t1 == TT);

            unsigned a0 = sm[W_Z + t0 * 8 + tig];
            unsigned a1 = sm[W_Z + t1 * 8 + tig];
            unsigned a2 = sm[W_Z + t0 * 8 + tig + 4];
            unsigned a3 = sm[W_Z + t1 * 8 + tig + 4];

            const float* orow0 = obsb + t0 * NN + 2 * tig;
            const float* orow1 = obsb + t1 * NN + 2 * tig;
            float2 qa0[4], qa1[4];
            #pragma unroll
            for (int c = 0; c < 4; c++) {
                qa0[c] = __ldcs(reinterpret_cast<const float2*>(orow0 + 8 * c));
                qa1[c] = __ldcs(reinterpret_cast<const float2*>(orow1 + 8 * c));
            }

            float acc0 = 0.0f, acc1 = 0.0f;
            #pragma unroll
            for (int ntl = 0; ntl < 4; ntl++) {
                const unsigned* Cb = sm + W_EM + s * 384 + (ntl * 8 + g) * 12;
                unsigned b0 = Cb[tig], b1 = Cb[tig + 4];
                float2 e = *reinterpret_cast<const float2*>(smf + W_EOF + s * 32 + ntl * 8 + 2 * tig);
                float d0, d1, d2, d3;
                mma16816(d0, d1, d2, d3, a0, a1, a2, a3, b0, b1,
                         qa0[ntl].x + e.x, qa0[ntl].y + e.y, qa1[ntl].x + e.x, qa1[ntl].y + e.y);
                float2 ea = *reinterpret_cast<const float2*>(smf + W_EA2 + s * 32 + ntl * 8 + 2 * tig);
                acc0 = fmaf(ea.x, d0 * d0, acc0); acc0 = fmaf(ea.y, d1 * d1, acc0);
                acc1 = fmaf(ea.x, d2 * d2, acc1); acc1 = fmaf(ea.y, d3 * d3, acc1);
            }

            int tp0 = f0 ? t0 : t0 - 1;
            int tp1 = f1 ? t1 : t1 - 1;
            unsigned p0 = sm[W_Z + tp0 * 8 + tig];
            unsigned p1 = sm[W_Z + tp1 * 8 + tig];
            unsigned p2 = sm[W_Z + tp0 * 8 + tig + 4];
            unsigned p3 = sm[W_Z + tp1 * 8 + tig + 4];
            float dac0 = 0.0f, dac1 = 0.0f;
            #pragma unroll
            for (int ntl = 0; ntl < 2; ntl++) {
                const unsigned* Ab = sm + W_DY + s * 192 + (ntl * 8 + g) * 12;
                unsigned b0 = Ab[tig], b1 = Ab[tig + 4];
                float2 df = *reinterpret_cast<const float2*>(smf + W_DOF + s * 16 + ntl * 8 + 2 * tig);
                float2 q0 = __half22float2(H2(sm[W_Z + t0 * 8 + ntl * 4 + tig]));
                float2 q1 = __half22float2(H2(sm[W_Z + t1 * 8 + ntl * 4 + tig]));
                float d0, d1, d2, d3;
                mma16816(d0, d1, d2, d3, p0, p1, p2, p3, b0, b1,
                         q0.x + df.x, q0.y + df.y, q1.x + df.x, q1.y + df.y);
                float2 da = *reinterpret_cast<const float2*>(smf + W_DA2 + s * 16 + ntl * 8 + 2 * tig);
                dac0 = fmaf(da.x, d0 * d0, dac0); dac0 = fmaf(da.y, d1 * d1, dac0);
                dac1 = fmaf(da.x, d2 * d2, dac1); dac1 = fmaf(da.y, d3 * d3, dac1);
            }

            float row0 = v0 ? (acc0 + (f0 ? 0.0f : dac0)) : 0.0f;
            float row1 = v1 ? (acc1 + (f1 ? 0.0f : dac1)) : 0.0f;
            row0 += __shfl_xor_sync(0xFFFFFFFFu, row0, 1);
            row0 += __shfl_xor_sync(0xFFFFFFFFu, row0, 2);
            row1 += __shfl_xor_sync(0xFFFFFFFFu, row1, 1);
            row1 += __shfl_xor_sync(0xFFFFFFFFu, row1, 2);

            if (tig == 0) {
                if (v0) {
                    float lp;
                    if (!f0) lp = smf[W_CT + s] + smf[W_TR + smi[W_SS + t0 - 1] * 8 + s];
                    else {
                        float iacc = 0.0f;
                        lp = smf[W_C0 + s];
                        #pragma unroll
                        for (int w = 0; w < 8; w++) {
                            float2 z = __half22float2(H2(sm[W_Z + t0 * 8 + w]));
                            float y0 = fmaf(z.x, smf[W_INA + s * 16 + 2 * w], smf[W_INB + s * 16 + 2 * w]);
                            float y1 = fmaf(z.y, smf[W_INA + s * 16 + 2 * w + 1], smf[W_INB + s * 16 + 2 * w + 1]);
                            iacc = fmaf(y0, y0, iacc); iacc = fmaf(y1, y1, iacc);
                        }
                        lp -= 0.5f * iacc;
                    }
                    float contrib = lp - 0.5f * row0;
                    if (t0 >= TT) part1 += contrib; else part0 += contrib;
                }
                if (v1) {
                    float lp;
                    if (!f1) lp = smf[W_CT + s] + smf[W_TR + smi[W_SS + t1 - 1] * 8 + s];
                    else {
                        float iacc = 0.0f;
                        lp = smf[W_C0 + s];
                        #pragma unroll
                        for (int w = 0; w < 8; w++) {
                            float2 z = __half22float2(H2(sm[W_Z + t1 * 8 + w]));
                            float y0 = fmaf(z.x, smf[W_INA + s * 16 + 2 * w], smf[W_INB + s * 16 + 2 * w]);
                            float y1 = fmaf(z.y, smf[W_INA + s * 16 + 2 * w + 1], smf[W_INB + s * 16 + 2 * w + 1]);
                            iacc = fmaf(y0, y0, iacc); iacc = fmaf(y1, y1, iacc);
                        }
                        lp -= 0.5f * iacc;
                    }
                    float contrib = lp - 0.5f * row1;
                    if (t1 >= TT) part1 += contrib; else part0 += contrib;
                }
            }
        }

        #pragma unroll
        for (int o = 16; o > 0; o >>= 1) {
            part0 += __shfl_xor_sync(0xFFFFFFFFu, part0, o);
            part1 += __shfl_xor_sync(0xFFFFFFFFu, part1, o);
        }
        if (lane == 0) { sRed0[warpid] = part0; sRed1[warpid] = part1; }
        __syncthreads();
        if (tid == 0) {
            float sum0 = 0.0f, sum1 = 0.0f;
            #pragma unroll
            for (int w = 0; w < TPB / 32; w++) { sum0 += sRed0[w]; sum1 += sRed1[w]; }
            out[2 * pb] = sum0;
            out[2 * pb + 1] = sum1;
        }
    }
}

extern "C" void kernel_launch(void* const* d_in, const int* in_sizes, int n_in,
                              void* d_out, int out_size)
{
    const int*   ds    = (const int*)  d_in[0];
    const float* cont  = (const float*)d_in[1];
    const float* obs   = (const float*)d_in[2];
    const float* il    = (const float*)d_in[3];
    const float* iloc  = (const float*)d_in[4];
    const float* ils   = (const float*)d_in[5];
    const float* trl   = (const float*)d_in[6];
    const float* dynM  = (const float*)d_in[7];
    const float* dynO  = (const float*)d_in[8];
    const float* dynS  = (const float*)d_in[9];
    const float* emM   = (const float*)d_in[10];
    const float* emO   = (const float*)d_in[11];
    const float* emS   = (const float*)d_in[12];
    float* out = (float*)d_out;

    stage1_kernel<<<GRID, TPB>>>(ds, cont, obs, il, iloc, ils, trl,
                                 dynM, dynO, dynS, emM, emO, emS, out);
}